// round 12
// baseline (speedup 1.0000x reference)
#include <cuda_runtime.h>
#include <cuda_fp16.h>
#include <cstdint>

#define MAXN 50000
#define MAXE 800000

// ---------------- scratch (device globals: no allocation allowed) ----------
// INVARIANT: g_deg is all-zero at the start of every launch. It is zero at
// module load, and k_agg64_last (the final consumer) re-zeroes it each launch.
__device__ __align__(16) int    g_deg[MAXN];
__device__ __align__(16) int    g_cursor[MAXN];   // = rowbeg after k_alloc
__device__ __align__(16) int    g_rowbeg[MAXN];
__device__ __align__(16) float  g_dis[MAXN];
__device__ __align__(16) int2   g_edge[MAXE];     // {col, __float_as_int(dis[col])}
__device__ int g_etot;
// ping-pong fp16 feature buffers (padded 128 rows: GEMM reads whole tiles)
__device__ __align__(16) __half g_fa[(size_t)(MAXN + 128) * 128];
__device__ __align__(16) __half g_fb[(size_t)(MAXN + 128) * 128];
// fp16 W fragments (m16n8k16 B order): L1@0 | L2@8192 | L3@24576
__device__ __align__(16) __half g_wf16[32768];

// fp16 MMA: D(16x8,f32) += A(16x16,f16) * B(16x8,f16)
__device__ __forceinline__ void mma_f16(float c[4], const unsigned a[4], uint2 b) {
    asm volatile(
        "mma.sync.aligned.m16n8k16.row.col.f32.f16.f16.f32 "
        "{%0,%1,%2,%3}, {%4,%5,%6,%7}, {%8,%9}, {%0,%1,%2,%3};"
        : "+f"(c[0]), "+f"(c[1]), "+f"(c[2]), "+f"(c[3])
        : "r"(a[0]), "r"(a[1]), "r"(a[2]), "r"(a[3]), "r"(b.x), "r"(b.y));
}

// ---------------- k_init: x->fp16 + W frags + degree count -----------------
// Exactly E = n*16 = 800000 threads; deg is zero on entry (invariant).
__global__ void k_init(const float* __restrict__ x,
                       const int* __restrict__ dst,
                       const float* __restrict__ W1,
                       const float* __restrict__ W2,
                       const float* __restrict__ W3, int E, int n) {
    int i = blockIdx.x * blockDim.x + threadIdx.x;
    if (i == 0) g_etot = 0;
    // x [n,64] fp32 -> g_fb fp16
    if (i < n * 16) {
        float4 v = ((const float4*)x)[i];
        __half2* o = (__half2*)g_fb + i * 2;
        o[0] = __floats2half2_rn(v.x, v.y);
        o[1] = __floats2half2_rn(v.z, v.w);
    }
    // W -> fp16 fragment order: thread t of quad owns k={2t,2t+1,2t+8,2t+9}
    if (i < 32768) {
        const float* W; int OUT, base, rel;
        if (i < 8192)       { W = W1; OUT = 128; base = 0;     rel = i; }
        else if (i < 24576) { W = W2; OUT = 128; base = 8192;  rel = i - 8192; }
        else                { W = W3; OUT = 64;  base = 24576; rel = i - 24576; }
        int k = rel / OUT, c = rel % OUT;
        int kc = k >> 4, kr = k & 15;
        int t   = (kr < 8) ? (kr >> 1) : ((kr - 8) >> 1);
        int pos = (kr < 8) ? (kr & 1) : (2 + (kr & 1));
        g_wf16[base + ((kc * OUT + c) << 4) + (t << 2) + pos] = __float2half(W[rel]);
    }
    // degree count (deg starts all-zero per invariant)
    if (i < E) {
        unsigned d = (unsigned)dst[i];
        if (d < (unsigned)n) atomicAdd(&g_deg[d], 1);
    }
}

// Disjoint contiguous row ranges via warp-aggregated atomic allocation.
// Also computes dis and seeds cursor = rowbeg.
__global__ void k_alloc(int n) {
    int i = blockIdx.x * blockDim.x + threadIdx.x;
    int lane = threadIdx.x & 31;
    int d = 0;
    if (i < n) {
        d = g_deg[i];
        g_dis[i] = rsqrtf((float)(d + 1));   // +1 self loop
    }
    int scan = d;
#pragma unroll
    for (int off = 1; off < 32; off <<= 1) {
        int v = __shfl_up_sync(0xffffffffu, scan, off);
        if (lane >= off) scan += v;
    }
    int tot = __shfl_sync(0xffffffffu, scan, 31);
    int base = 0;
    if (lane == 0) base = atomicAdd(&g_etot, tot);
    base = __shfl_sync(0xffffffffu, base, 0);
    if (i < n) {
        int rb = base + scan - d;
        g_rowbeg[i] = rb;
        g_cursor[i] = rb;
    }
}

// Edge record stores only dis[src]; dis[dst] applied once per node in agg.
__global__ void k_fill(const int* __restrict__ src,
                       const int* __restrict__ dst, int E, int n) {
    int i = blockIdx.x * blockDim.x + threadIdx.x;
    if (i < E) {
        unsigned s = (unsigned)src[i];
        unsigned d = (unsigned)dst[i];
        if (s < (unsigned)n && d < (unsigned)n) {
            int pos = atomicAdd(&g_cursor[d], 1);
            g_edge[pos] = make_int2((int)s, __float_as_int(g_dis[s]));
        }
    }
}

// ---------------- aggregation: out[d] = ds*(Σ dis_s·u_s + ds·v_d) -----------
struct __align__(8) h4 { __half2 a, b; };

__global__ void k_agg128(int n) {
    int warp = (blockIdx.x * blockDim.x + threadIdx.x) >> 5;
    int lane = threadIdx.x & 31;
    if (warp >= n) return;
    const __half* in = g_fb;
    float ds = g_dis[warp];
    h4 sv = ((const h4*)(in + (size_t)warp * 128))[lane];
    float2 s0 = __half22float2(sv.a), s1 = __half22float2(sv.b);
    float4 acc = make_float4(ds * s0.x, ds * s0.y, ds * s1.x, ds * s1.y);
    int beg = g_rowbeg[warp], end = beg + g_deg[warp];
    for (int base = beg; base < end; base += 32) {
        int idx = base + lane;
        int2 e = make_int2(0, 0);
        if (idx < end) e = g_edge[idx];
        int m = min(32, end - base);
        for (int t = 0; t < m; t++) {
            int s   = __shfl_sync(0xffffffffu, e.x, t);
            float w = __int_as_float(__shfl_sync(0xffffffffu, e.y, t));
            h4 u = ((const h4*)(in + (size_t)s * 128))[lane];
            float2 f0 = __half22float2(u.a), f1 = __half22float2(u.b);
            acc.x += w * f0.x; acc.y += w * f0.y;
            acc.z += w * f1.x; acc.w += w * f1.y;
        }
    }
    h4 o;
    o.a = __floats2half2_rn(ds * acc.x, ds * acc.y);
    o.b = __floats2half2_rn(ds * acc.z, ds * acc.w);
    ((h4*)(g_fa + (size_t)warp * 128))[lane] = o;
}

__global__ void k_agg64_first(int n) {
    int warp = (blockIdx.x * blockDim.x + threadIdx.x) >> 5;
    int lane = threadIdx.x & 31;
    if (warp >= n) return;
    const __half* in = g_fb;
    float ds = g_dis[warp];
    float2 v = __half22float2(((const __half2*)(in + (size_t)warp * 64))[lane]);
    float2 acc = make_float2(ds * v.x, ds * v.y);
    int beg = g_rowbeg[warp], end = beg + g_deg[warp];
    for (int base = beg; base < end; base += 32) {
        int idx = base + lane;
        int2 e = make_int2(0, 0);
        if (idx < end) e = g_edge[idx];
        int m = min(32, end - base);
        for (int t = 0; t < m; t++) {
            int s   = __shfl_sync(0xffffffffu, e.x, t);
            float w = __int_as_float(__shfl_sync(0xffffffffu, e.y, t));
            float2 u = __half22float2(((const __half2*)(in + (size_t)s * 64))[lane]);
            acc.x += w * u.x; acc.y += w * u.y;
        }
    }
    ((__half2*)(g_fa + (size_t)warp * 64))[lane] =
        __floats2half2_rn(ds * acc.x, ds * acc.y);
}

// last agg: reads g_fa (GEMM3 out), + b3, fp32 out. Restores deg=0 invariant.
__global__ void k_agg64_last(float* __restrict__ out,
                             const float* __restrict__ bias, int n) {
    int warp = (blockIdx.x * blockDim.x + threadIdx.x) >> 5;
    int lane = threadIdx.x & 31;
    if (warp >= n) return;
    const __half* in = g_fa;
    float ds = g_dis[warp];
    float2 v = __half22float2(((const __half2*)(in + (size_t)warp * 64))[lane]);
    float2 acc = make_float2(ds * v.x, ds * v.y);
    int beg = g_rowbeg[warp], end = beg + g_deg[warp];
    if (lane == 0) g_deg[warp] = 0;   // restore invariant for next launch
    for (int base = beg; base < end; base += 32) {
        int idx = base + lane;
        int2 e = make_int2(0, 0);
        if (idx < end) e = g_edge[idx];
        int m = min(32, end - base);
        for (int t = 0; t < m; t++) {
            int s   = __shfl_sync(0xffffffffu, e.x, t);
            float w = __int_as_float(__shfl_sync(0xffffffffu, e.y, t));
            float2 u = __half22float2(((const __half2*)(in + (size_t)s * 64))[lane]);
            acc.x += w * u.x; acc.y += w * u.y;
        }
    }
    acc.x = ds * acc.x + bias[lane * 2];
    acc.y = ds * acc.y + bias[lane * 2 + 1];
    ((float2*)(out + (size_t)warp * 64))[lane] = acc;
}

// ---------------- smem-free fp16 tensor GEMM --------------------------------
// DIR: 0 = read g_fa / write g_fb;  1 = read g_fb / write g_fa
template <int IN, int OUT, bool BIAS, bool RELU, int DIR>
__global__ void __launch_bounds__(128) k_gemm16(const float* __restrict__ bias,
                                                int wbase, int n) {
    constexpr int NT = OUT / 8;
    const __half* X = DIR == 0 ? g_fa : g_fb;
    __half* Y = DIR == 0 ? g_fb : g_fa;
    const __half* WF = g_wf16 + wbase;

    int tid = threadIdx.x;
    int w = tid >> 5, lane = tid & 31, g = lane >> 2, t = lane & 3;
    int row0 = blockIdx.x * 128 + w * 32 + g;

    float acc[2][NT][4];
#pragma unroll
    for (int m = 0; m < 2; m++)
#pragma unroll
        for (int nt = 0; nt < NT; nt++)
#pragma unroll
            for (int q = 0; q < 4; q++) acc[m][nt][q] = 0.f;

#pragma unroll
    for (int kc = 0; kc < IN / 16; kc++) {
        unsigned a[2][4];
#pragma unroll
        for (int m = 0; m < 2; m++) {
            size_t r = (size_t)(row0 + m * 16);
            const __half* xp = X + r * IN + kc * 16 + 2 * t;
            a[m][0] = *(const unsigned*)(xp);
            a[m][1] = *(const unsigned*)(xp + 8 * IN);
            a[m][2] = *(const unsigned*)(xp + 8);
            a[m][3] = *(const unsigned*)(xp + 8 * IN + 8);
        }
#pragma unroll
        for (int nt = 0; nt < NT; nt++) {
            uint2 b = *(const uint2*)(WF + ((kc * OUT + nt * 8 + g) << 4) + (t << 2));
            mma_f16(acc[0][nt], a[0], b);
            mma_f16(acc[1][nt], a[1], b);
        }
    }

#pragma unroll
    for (int m = 0; m < 2; m++) {
        int r = row0 + m * 16;
#pragma unroll
        for (int nt = 0; nt < NT; nt++) {
            int c = nt * 8 + t * 2;
            float2 p0 = make_float2(acc[m][nt][0], acc[m][nt][1]);
            float2 p1 = make_float2(acc[m][nt][2], acc[m][nt][3]);
            if (BIAS) {
                float2 bb = *(const float2*)(bias + c);
                p0.x += bb.x; p0.y += bb.y; p1.x += bb.x; p1.y += bb.y;
            }
            if (RELU) {
                p0.x = fmaxf(p0.x, 0.f); p0.y = fmaxf(p0.y, 0.f);
                p1.x = fmaxf(p1.x, 0.f); p1.y = fmaxf(p1.y, 0.f);
            }
            if (r < n)
                *(__half2*)(Y + (size_t)r * OUT + c) = __floats2half2_rn(p0.x, p0.y);
            if (r + 8 < n)
                *(__half2*)(Y + (size_t)(r + 8) * OUT + c) = __floats2half2_rn(p1.x, p1.y);
        }
    }
}

// ---------------- launch ----------------------------------------------------
extern "C" void kernel_launch(void* const* d_in, const int* in_sizes, int n_in,
                              void* d_out, int out_size) {
    const float* x  = (const float*)d_in[0];
    const int*   ei = (const int*)d_in[1];   // int32 (JAX x64 disabled)
    const float* W1 = (const float*)d_in[2];
    const float* b1 = (const float*)d_in[3];
    const float* W2 = (const float*)d_in[4];
    const float* b2 = (const float*)d_in[5];
    const float* W3 = (const float*)d_in[6];
    const float* b3 = (const float*)d_in[7];
    float* out = (float*)d_out;

    const int n = in_sizes[0] / 64;   // 50000
    const int E = in_sizes[1] / 2;    // 800000
    const int* src = ei;
    const int* dst = ei + E;

    const int T = 256;
    const int initThreads = (n * 16 > E) ? n * 16 : E;   // both 800000

    // --- preprocessing: 3 launches ---
    k_init<<<(initThreads + T - 1) / T, T>>>(x, dst, W1, W2, W3, E, n);  // x->fb, W, count
    k_alloc<<<(n + T - 1) / T, T>>>(n);
    k_fill<<<(E + T - 1) / T, T>>>(src, dst, E, n);

    const int aggGrid = (n + 7) / 8;      // 8 warps/block
    const int gemmGrid = (n + 127) / 128; // 391

    // L1: agg(x in fb) -> fa ; fa @ W1 +b1 relu -> fb
    k_agg64_first<<<aggGrid, T>>>(n);
    k_gemm16<64, 128, true, true, 0><<<gemmGrid, 128>>>(b1, 0, n);

    // L2: agg(fb) -> fa ; fa @ W2 +b2 relu -> fb
    k_agg128<<<aggGrid, T>>>(n);
    k_gemm16<128, 128, true, true, 0><<<gemmGrid, 128>>>(b2, 8192, n);

    // L3: fb @ W3 -> fa ; agg(fa) + b3 -> out
    k_gemm16<128, 64, false, false, 1><<<gemmGrid, 128>>>(nullptr, 24576, n);
    k_agg64_last<<<aggGrid, T>>>(out, b3, n);
}

// round 14
// speedup vs baseline: 1.1884x; 1.1884x over previous
#include <cuda_runtime.h>
#include <cuda_fp16.h>
#include <cstdint>

#define MAXN 50000
#define MAXE 800000

// ---------------- scratch (device globals: no allocation allowed) ----------
__device__ __align__(16) int    g_deg[MAXN];
__device__ __align__(16) int    g_cursor[MAXN];   // seeded = rowbeg by k_alloc
__device__ __align__(16) int    g_rowbeg[MAXN];
__device__ __align__(16) float  g_dis[MAXN];
__device__ __align__(16) int2   g_edge[MAXE];     // {src, __float_as_int(dis[src])}
__device__ int g_etot;
// ping-pong fp16 feature buffers (padded 128 rows: GEMM reads whole tiles)
__device__ __align__(16) __half g_fa[(size_t)(MAXN + 128) * 128];
__device__ __align__(16) __half g_fb[(size_t)(MAXN + 128) * 128];
// fp16 W fragments (m16n8k16 B order): L1@0 | L2@8192 | L3@24576
__device__ __align__(16) __half g_wf16[32768];

// fp16 MMA: D(16x8,f32) += A(16x16,f16) * B(16x8,f16)
__device__ __forceinline__ void mma_f16(float c[4], const unsigned a[4], uint2 b) {
    asm volatile(
        "mma.sync.aligned.m16n8k16.row.col.f32.f16.f16.f32 "
        "{%0,%1,%2,%3}, {%4,%5,%6,%7}, {%8,%9}, {%0,%1,%2,%3};"
        : "+f"(c[0]), "+f"(c[1]), "+f"(c[2]), "+f"(c[3])
        : "r"(a[0]), "r"(a[1]), "r"(a[2]), "r"(a[3]), "r"(b.x), "r"(b.y));
}

// ---------------- k_init: zero deg + x->fp16 + W frags ----------------------
__global__ void k_init(const float* __restrict__ x,
                       const float* __restrict__ W1,
                       const float* __restrict__ W2,
                       const float* __restrict__ W3, int n) {
    int i = blockIdx.x * blockDim.x + threadIdx.x;
    if (i == 0) g_etot = 0;
    if (i < n * 16) {
        float4 v = ((const float4*)x)[i];
        __half2* o = (__half2*)g_fb + i * 2;
        o[0] = __floats2half2_rn(v.x, v.y);
        o[1] = __floats2half2_rn(v.z, v.w);
    }
    // W -> fp16 fragment order: thread t of quad owns k={2t,2t+1,2t+8,2t+9}
    if (i < 32768) {
        const float* W; int OUT, base, rel;
        if (i < 8192)       { W = W1; OUT = 128; base = 0;     rel = i; }
        else if (i < 24576) { W = W2; OUT = 128; base = 8192;  rel = i - 8192; }
        else                { W = W3; OUT = 64;  base = 24576; rel = i - 24576; }
        int k = rel / OUT, c = rel % OUT;
        int kc = k >> 4, kr = k & 15;
        int t   = (kr < 8) ? (kr >> 1) : ((kr - 8) >> 1);
        int pos = (kr < 8) ? (kr & 1) : (2 + (kr & 1));
        g_wf16[base + ((kc * OUT + c) << 4) + (t << 2) + pos] = __float2half(W[rel]);
    }
    if (i < n) g_deg[i] = 0;
}

__global__ void k_count(const int* __restrict__ dst, int E, int n) {
    int i = blockIdx.x * blockDim.x + threadIdx.x;
    if (i < E) {
        unsigned d = (unsigned)dst[i];
        if (d < (unsigned)n) atomicAdd(&g_deg[d], 1);
    }
}

// Disjoint contiguous row ranges via warp-aggregated atomic allocation.
__global__ void k_alloc(int n) {
    int i = blockIdx.x * blockDim.x + threadIdx.x;
    int lane = threadIdx.x & 31;
    int d = 0;
    if (i < n) {
        d = g_deg[i];
        g_dis[i] = rsqrtf((float)(d + 1));   // +1 self loop
    }
    int scan = d;
#pragma unroll
    for (int off = 1; off < 32; off <<= 1) {
        int v = __shfl_up_sync(0xffffffffu, scan, off);
        if (lane >= off) scan += v;
    }
    int tot = __shfl_sync(0xffffffffu, scan, 31);
    int base = 0;
    if (lane == 0) base = atomicAdd(&g_etot, tot);
    base = __shfl_sync(0xffffffffu, base, 0);
    if (i < n) {
        int rb = base + scan - d;
        g_rowbeg[i] = rb;
        g_cursor[i] = rb;
    }
}

__global__ void k_fill(const int* __restrict__ src,
                       const int* __restrict__ dst, int E, int n) {
    int i = blockIdx.x * blockDim.x + threadIdx.x;
    if (i < E) {
        unsigned s = (unsigned)src[i];
        unsigned d = (unsigned)dst[i];
        if (s < (unsigned)n && d < (unsigned)n) {
            int pos = atomicAdd(&g_cursor[d], 1);
            g_edge[pos] = make_int2((int)s, __float_as_int(g_dis[s]));
        }
    }
}

// ---------------- aggregation: out[d] = ds*(ds*v_d + Σ dis_s·u_s) -----------
// 4-wide software-pipelined gathers (MLP=4) with two accumulator chains.
struct __align__(8) h4 { __half2 a, b; };

#define SHFL_EDGE(k)                                              \
    int s##k = __shfl_sync(0xffffffffu, e.x, t + k);              \
    float w##k = __int_as_float(__shfl_sync(0xffffffffu, e.y, t + k));

__global__ void k_agg128(int n) {
    int warp = (blockIdx.x * blockDim.x + threadIdx.x) >> 5;
    int lane = threadIdx.x & 31;
    if (warp >= n) return;
    const __half* in = g_fb;
    float ds = g_dis[warp];
    h4 sv = ((const h4*)(in + (size_t)warp * 128))[lane];
    float2 s0v = __half22float2(sv.a), s1v = __half22float2(sv.b);
    float4 acc  = make_float4(ds * s0v.x, ds * s0v.y, ds * s1v.x, ds * s1v.y);
    float4 acc2 = make_float4(0.f, 0.f, 0.f, 0.f);
    int beg = g_rowbeg[warp], end = beg + g_deg[warp];
    for (int base = beg; base < end; base += 32) {
        int idx = base + lane;
        int2 e = make_int2(0, 0);
        if (idx < end) e = g_edge[idx];
        int m = min(32, end - base);
        int t = 0;
        for (; t + 4 <= m; t += 4) {
            SHFL_EDGE(0) SHFL_EDGE(1) SHFL_EDGE(2) SHFL_EDGE(3)
            h4 u0 = ((const h4*)(in + (size_t)s0 * 128))[lane];
            h4 u1 = ((const h4*)(in + (size_t)s1 * 128))[lane];
            h4 u2 = ((const h4*)(in + (size_t)s2 * 128))[lane];
            h4 u3 = ((const h4*)(in + (size_t)s3 * 128))[lane];
            float2 a0 = __half22float2(u0.a), b0 = __half22float2(u0.b);
            float2 a1 = __half22float2(u1.a), b1 = __half22float2(u1.b);
            float2 a2 = __half22float2(u2.a), b2 = __half22float2(u2.b);
            float2 a3 = __half22float2(u3.a), b3 = __half22float2(u3.b);
            acc.x  += w0 * a0.x; acc.y  += w0 * a0.y; acc.z  += w0 * b0.x; acc.w  += w0 * b0.y;
            acc2.x += w1 * a1.x; acc2.y += w1 * a1.y; acc2.z += w1 * b1.x; acc2.w += w1 * b1.y;
            acc.x  += w2 * a2.x; acc.y  += w2 * a2.y; acc.z  += w2 * b2.x; acc.w  += w2 * b2.y;
            acc2.x += w3 * a3.x; acc2.y += w3 * a3.y; acc2.z += w3 * b3.x; acc2.w += w3 * b3.y;
        }
        for (; t < m; t++) {
            SHFL_EDGE(0)
            h4 u = ((const h4*)(in + (size_t)s0 * 128))[lane];
            float2 f0 = __half22float2(u.a), f1 = __half22float2(u.b);
            acc.x += w0 * f0.x; acc.y += w0 * f0.y;
            acc.z += w0 * f1.x; acc.w += w0 * f1.y;
        }
    }
    h4 o;
    o.a = __floats2half2_rn(ds * (acc.x + acc2.x), ds * (acc.y + acc2.y));
    o.b = __floats2half2_rn(ds * (acc.z + acc2.z), ds * (acc.w + acc2.w));
    ((h4*)(g_fa + (size_t)warp * 128))[lane] = o;
}

__global__ void k_agg64_first(int n) {
    int warp = (blockIdx.x * blockDim.x + threadIdx.x) >> 5;
    int lane = threadIdx.x & 31;
    if (warp >= n) return;
    const __half* in = g_fb;
    float ds = g_dis[warp];
    float2 v = __half22float2(((const __half2*)(in + (size_t)warp * 64))[lane]);
    float2 acc  = make_float2(ds * v.x, ds * v.y);
    float2 acc2 = make_float2(0.f, 0.f);
    int beg = g_rowbeg[warp], end = beg + g_deg[warp];
    for (int base = beg; base < end; base += 32) {
        int idx = base + lane;
        int2 e = make_int2(0, 0);
        if (idx < end) e = g_edge[idx];
        int m = min(32, end - base);
        int t = 0;
        for (; t + 4 <= m; t += 4) {
            SHFL_EDGE(0) SHFL_EDGE(1) SHFL_EDGE(2) SHFL_EDGE(3)
            float2 u0 = __half22float2(((const __half2*)(in + (size_t)s0 * 64))[lane]);
            float2 u1 = __half22float2(((const __half2*)(in + (size_t)s1 * 64))[lane]);
            float2 u2 = __half22float2(((const __half2*)(in + (size_t)s2 * 64))[lane]);
            float2 u3 = __half22float2(((const __half2*)(in + (size_t)s3 * 64))[lane]);
            acc.x  += w0 * u0.x; acc.y  += w0 * u0.y;
            acc2.x += w1 * u1.x; acc2.y += w1 * u1.y;
            acc.x  += w2 * u2.x; acc.y  += w2 * u2.y;
            acc2.x += w3 * u3.x; acc2.y += w3 * u3.y;
        }
        for (; t < m; t++) {
            SHFL_EDGE(0)
            float2 u = __half22float2(((const __half2*)(in + (size_t)s0 * 64))[lane]);
            acc.x += w0 * u.x; acc.y += w0 * u.y;
        }
    }
    ((__half2*)(g_fa + (size_t)warp * 64))[lane] =
        __floats2half2_rn(ds * (acc.x + acc2.x), ds * (acc.y + acc2.y));
}

__global__ void k_agg64_last(float* __restrict__ out,
                             const float* __restrict__ bias, int n) {
    int warp = (blockIdx.x * blockDim.x + threadIdx.x) >> 5;
    int lane = threadIdx.x & 31;
    if (warp >= n) return;
    const __half* in = g_fa;
    float ds = g_dis[warp];
    float2 v = __half22float2(((const __half2*)(in + (size_t)warp * 64))[lane]);
    float2 acc  = make_float2(ds * v.x, ds * v.y);
    float2 acc2 = make_float2(0.f, 0.f);
    int beg = g_rowbeg[warp], end = beg + g_deg[warp];
    for (int base = beg; base < end; base += 32) {
        int idx = base + lane;
        int2 e = make_int2(0, 0);
        if (idx < end) e = g_edge[idx];
        int m = min(32, end - base);
        int t = 0;
        for (; t + 4 <= m; t += 4) {
            SHFL_EDGE(0) SHFL_EDGE(1) SHFL_EDGE(2) SHFL_EDGE(3)
            float2 u0 = __half22float2(((const __half2*)(in + (size_t)s0 * 64))[lane]);
            float2 u1 = __half22float2(((const __half2*)(in + (size_t)s1 * 64))[lane]);
            float2 u2 = __half22float2(((const __half2*)(in + (size_t)s2 * 64))[lane]);
            float2 u3 = __half22float2(((const __half2*)(in + (size_t)s3 * 64))[lane]);
            acc.x  += w0 * u0.x; acc.y  += w0 * u0.y;
            acc2.x += w1 * u1.x; acc2.y += w1 * u1.y;
            acc.x  += w2 * u2.x; acc.y  += w2 * u2.y;
            acc2.x += w3 * u3.x; acc2.y += w3 * u3.y;
        }
        for (; t < m; t++) {
            SHFL_EDGE(0)
            float2 u = __half22float2(((const __half2*)(in + (size_t)s0 * 64))[lane]);
            acc.x += w0 * u.x; acc.y += w0 * u.y;
        }
    }
    float2 r;
    r.x = ds * (acc.x + acc2.x) + bias[lane * 2];
    r.y = ds * (acc.y + acc2.y) + bias[lane * 2 + 1];
    ((float2*)(out + (size_t)warp * 64))[lane] = r;
}

// ---------------- smem-free fp16 tensor GEMM --------------------------------
// DIR: 0 = read g_fa / write g_fb;  1 = read g_fb / write g_fa
template <int IN, int OUT, bool BIAS, bool RELU, int DIR>
__global__ void __launch_bounds__(128) k_gemm16(const float* __restrict__ bias,
                                                int wbase, int n) {
    constexpr int NT = OUT / 8;
    const __half* X = DIR == 0 ? g_fa : g_fb;
    __half* Y = DIR == 0 ? g_fb : g_fa;
    const __half* WF = g_wf16 + wbase;

    int tid = threadIdx.x;
    int w = tid >> 5, lane = tid & 31, g = lane >> 2, t = lane & 3;
    int row0 = blockIdx.x * 128 + w * 32 + g;

    float acc[2][NT][4];
#pragma unroll
    for (int m = 0; m < 2; m++)
#pragma unroll
        for (int nt = 0; nt < NT; nt++)
#pragma unroll
            for (int q = 0; q < 4; q++) acc[m][nt][q] = 0.f;

#pragma unroll
    for (int kc = 0; kc < IN / 16; kc++) {
        unsigned a[2][4];
#pragma unroll
        for (int m = 0; m < 2; m++) {
            size_t r = (size_t)(row0 + m * 16);
            const __half* xp = X + r * IN + kc * 16 + 2 * t;
            a[m][0] = *(const unsigned*)(xp);
            a[m][1] = *(const unsigned*)(xp + 8 * IN);
            a[m][2] = *(const unsigned*)(xp + 8);
            a[m][3] = *(const unsigned*)(xp + 8 * IN + 8);
        }
#pragma unroll
        for (int nt = 0; nt < NT; nt++) {
            uint2 b = *(const uint2*)(WF + ((kc * OUT + nt * 8 + g) << 4) + (t << 2));
            mma_f16(acc[0][nt], a[0], b);
            mma_f16(acc[1][nt], a[1], b);
        }
    }

#pragma unroll
    for (int m = 0; m < 2; m++) {
        int r = row0 + m * 16;
#pragma unroll
        for (int nt = 0; nt < NT; nt++) {
            int c = nt * 8 + t * 2;
            float2 p0 = make_float2(acc[m][nt][0], acc[m][nt][1]);
            float2 p1 = make_float2(acc[m][nt][2], acc[m][nt][3]);
            if (BIAS) {
                float2 bb = *(const float2*)(bias + c);
                p0.x += bb.x; p0.y += bb.y; p1.x += bb.x; p1.y += bb.y;
            }
            if (RELU) {
                p0.x = fmaxf(p0.x, 0.f); p0.y = fmaxf(p0.y, 0.f);
                p1.x = fmaxf(p1.x, 0.f); p1.y = fmaxf(p1.y, 0.f);
            }
            if (r < n)
                *(__half2*)(Y + (size_t)r * OUT + c) = __floats2half2_rn(p0.x, p0.y);
            if (r + 8 < n)
                *(__half2*)(Y + (size_t)(r + 8) * OUT + c) = __floats2half2_rn(p1.x, p1.y);
        }
    }
}

// ---------------- launch ----------------------------------------------------
extern "C" void kernel_launch(void* const* d_in, const int* in_sizes, int n_in,
                              void* d_out, int out_size) {
    const float* x  = (const float*)d_in[0];
    const int*   ei = (const int*)d_in[1];   // int32 (JAX x64 disabled)
    const float* W1 = (const float*)d_in[2];
    const float* b1 = (const float*)d_in[3];
    const float* W2 = (const float*)d_in[4];
    const float* b2 = (const float*)d_in[5];
    const float* W3 = (const float*)d_in[6];
    const float* b3 = (const float*)d_in[7];
    float* out = (float*)d_out;

    const int n = in_sizes[0] / 64;   // 50000
    const int E = in_sizes[1] / 2;    // 800000
    const int* src = ei;
    const int* dst = ei + E;

    const int T = 256;

    // --- preprocessing: 4 launches ---
    k_init<<<(n * 16 + T - 1) / T, T>>>(x, W1, W2, W3, n);   // x -> fb, W frags
    k_count<<<(E + T - 1) / T, T>>>(dst, E, n);
    k_alloc<<<(n + T - 1) / T, T>>>(n);
    k_fill<<<(E + T - 1) / T, T>>>(src, dst, E, n);

    const int aggGrid = (n + 7) / 8;      // 8 warps/block
    const int gemmGrid = (n + 127) / 128; // 391

    // L1: agg(x in fb) -> fa ; fa @ W1 +b1 relu -> fb
    k_agg64_first<<<aggGrid, T>>>(n);
    k_gemm16<64, 128, true, true, 0><<<gemmGrid, 128>>>(b1, 0, n);

    // L2: agg(fb) -> fa ; fa @ W2 +b2 relu -> fb
    k_agg128<<<aggGrid, T>>>(n);
    k_gemm16<128, 128, true, true, 0><<<gemmGrid, 128>>>(b2, 8192, n);

    // L3: fb @ W3 -> fa ; agg(fa) + b3 -> out
    k_gemm16<128, 64, false, false, 1><<<gemmGrid, 128>>>(nullptr, 24576, n);
    k_agg64_last<<<aggGrid, T>>>(out, b3, n);
}